// round 1
// baseline (speedup 1.0000x reference)
#include <cuda_runtime.h>

#define BATCH 4
#define T_SEQ 2048
#define C_EMB 1024
#define NH 16
#define HD 64
#define C3 (3 * C_EMB)
#define M_ROWS (BATCH * T_SEQ)

// Scratch: __device__ globals (runtime allocation is forbidden).
__device__ float g_qkv[(size_t)M_ROWS * C3];     // [8192, 3072]
__device__ float g_y[(size_t)M_ROWS * C_EMB];    // [8192, 1024] attention output

// ---------------------------------------------------------------------------
// GEMM: C[M,N] = A[M,K] @ B[K,N] + bias[N].  128x128x16 tile, 8x8 micro-tile.
// M,N divisible by 128; K divisible by 16 (true for all our shapes).
// ---------------------------------------------------------------------------
__global__ __launch_bounds__(256) void gemm_bias_kernel(
    const float* __restrict__ A, const float* __restrict__ B,
    const float* __restrict__ bias, float* __restrict__ C,
    int M, int N, int K)
{
    const int BK = 16;
    __shared__ float As[16][128];   // transposed: As[k][m]
    __shared__ float Bs[16][128];

    int tid = threadIdx.x;
    int tx = tid & 15;          // 0..15 -> col group
    int ty = tid >> 4;          // 0..15 -> row group
    int rowBase = blockIdx.y * 128;
    int colBase = blockIdx.x * 128;

    // A-tile load mapping: 128 rows x 16 cols, 2 float4 per thread
    int a_r = tid >> 2;             // 0..63
    int a_c = (tid & 3) << 2;       // 0,4,8,12
    // B-tile load mapping: 16 rows x 128 cols, 2 float4 per thread (coalesced)
    int b_r = tid >> 5;             // 0..7
    int b_c = (tid & 31) << 2;      // 0..124

    const float* Aptr = A + (size_t)rowBase * K;
    const float* Bptr = B + colBase;

    float acc[8][8];
    #pragma unroll
    for (int i = 0; i < 8; i++)
        #pragma unroll
        for (int j = 0; j < 8; j++) acc[i][j] = 0.0f;

    for (int kt = 0; kt < K; kt += BK) {
        #pragma unroll
        for (int i = 0; i < 2; i++) {
            int r = a_r + i * 64;
            float4 v = *(const float4*)(Aptr + (size_t)r * K + kt + a_c);
            As[a_c + 0][r] = v.x;
            As[a_c + 1][r] = v.y;
            As[a_c + 2][r] = v.z;
            As[a_c + 3][r] = v.w;
        }
        #pragma unroll
        for (int i = 0; i < 2; i++) {
            int r = b_r + i * 8;
            *(float4*)&Bs[r][b_c] = *(const float4*)(Bptr + (size_t)(kt + r) * N + b_c);
        }
        __syncthreads();

        #pragma unroll
        for (int kk = 0; kk < BK; kk++) {
            float ra[8], rb[8];
            *(float4*)&ra[0] = *(const float4*)&As[kk][ty * 8];
            *(float4*)&ra[4] = *(const float4*)&As[kk][ty * 8 + 4];
            *(float4*)&rb[0] = *(const float4*)&Bs[kk][tx * 8];
            *(float4*)&rb[4] = *(const float4*)&Bs[kk][tx * 8 + 4];
            #pragma unroll
            for (int i = 0; i < 8; i++)
                #pragma unroll
                for (int j = 0; j < 8; j++)
                    acc[i][j] = fmaf(ra[i], rb[j], acc[i][j]);
        }
        __syncthreads();
    }

    #pragma unroll
    for (int i = 0; i < 8; i++) {
        size_t r = (size_t)rowBase + ty * 8 + i;
        #pragma unroll
        for (int j = 0; j < 8; j += 4) {
            int c = colBase + tx * 8 + j;
            float4 o;
            o.x = acc[i][j + 0] + bias[c + 0];
            o.y = acc[i][j + 1] + bias[c + 1];
            o.z = acc[i][j + 2] + bias[c + 2];
            o.w = acc[i][j + 3] + bias[c + 3];
            *(float4*)&C[r * N + c] = o;
        }
    }
}

// ---------------------------------------------------------------------------
// Flash attention (causal), fp32. Br=Bc=64, D=64, 256 threads.
// Thread (r = tid/4, q4 = tid%4):
//   score phase : cols c = q4 + 4*j   (j=0..15)   -> conflict-free K f4 reads
//   PV phase    : dims  d = 16*jj + 4*q4 + e      -> conflict-free V f4 reads
// smem rows padded to 68 floats so bank = (4*row + col) mod 32.
// ---------------------------------------------------------------------------
#define BR 64
#define BC 64
#define SPAD 68
#define ATTN_SMEM_FLOATS (2 * BR * SPAD + 2 * BC * SPAD)
#define ATTN_SMEM_BYTES (ATTN_SMEM_FLOATS * 4)

__global__ __launch_bounds__(256) void attn_kernel(
    const float* __restrict__ qkv, float* __restrict__ y)
{
    extern __shared__ float smem[];
    float* Qs = smem;                  // [BR][SPAD]
    float* Ks = Qs + BR * SPAD;        // [BC][SPAD]
    float* Vs = Ks + BC * SPAD;        // [BC][SPAD]
    float* Ps = Vs + BC * SPAD;        // [BR][SPAD]

    int qt = blockIdx.x;               // q tile (0..31)
    int h  = blockIdx.y;               // head
    int b  = blockIdx.z;               // batch
    int tid = threadIdx.x;
    int r  = tid >> 2;                 // row within tile
    int q4 = tid & 3;                  // quad lane

    // Load Q tile (once per block)
    const float* qbase = qkv + (size_t)(b * T_SEQ + qt * BR) * C3 + h * HD;
    #pragma unroll
    for (int i = 0; i < 4; i++) {
        int idx = tid + 256 * i;       // 0..1023 float4s
        int row = idx >> 4;
        int c4  = (idx & 15) << 2;
        *(float4*)&Qs[row * SPAD + c4] = *(const float4*)(qbase + (size_t)row * C3 + c4);
    }

    float m_i = -1e30f, l_i = 0.0f;
    float o[16];
    #pragma unroll
    for (int j = 0; j < 16; j++) o[j] = 0.0f;
    const float scale = 0.125f;        // 1/sqrt(64)

    for (int kt = 0; kt <= qt; kt++) {
        const float* kbase = qkv + (size_t)(b * T_SEQ + kt * BC) * C3 + C_EMB + h * HD;
        const float* vbase = kbase + C_EMB;

        __syncthreads();   // previous iteration done with Ks/Vs
        #pragma unroll
        for (int i = 0; i < 4; i++) {
            int idx = tid + 256 * i;
            int row = idx >> 4;
            int c4  = (idx & 15) << 2;
            *(float4*)&Ks[row * SPAD + c4] = *(const float4*)(kbase + (size_t)row * C3 + c4);
            *(float4*)&Vs[row * SPAD + c4] = *(const float4*)(vbase + (size_t)row * C3 + c4);
        }
        __syncthreads();

        // ---- scores S[r][c] = sum_d Q[r][d] * K[c][d], c = q4 + 4j
        float s[16];
        #pragma unroll
        for (int j = 0; j < 16; j++) s[j] = 0.0f;
        #pragma unroll 4
        for (int d4 = 0; d4 < 16; d4++) {
            float4 qv = *(const float4*)&Qs[r * SPAD + 4 * d4];
            #pragma unroll
            for (int j = 0; j < 16; j++) {
                float4 kv = *(const float4*)&Ks[(q4 + 4 * j) * SPAD + 4 * d4];
                s[j] = fmaf(qv.x, kv.x, fmaf(qv.y, kv.y,
                       fmaf(qv.z, kv.z, fmaf(qv.w, kv.w, s[j]))));
            }
        }

        // ---- causal mask + online softmax (row stats across quad via shfl)
        bool diag = (kt == qt);
        float mx = m_i;
        #pragma unroll
        for (int j = 0; j < 16; j++) {
            int c = q4 + 4 * j;
            float v = s[j] * scale;
            if (diag && c > r) v = -1e30f;
            s[j] = v;
            mx = fmaxf(mx, v);
        }
        mx = fmaxf(mx, __shfl_xor_sync(0xffffffffu, mx, 1));
        mx = fmaxf(mx, __shfl_xor_sync(0xffffffffu, mx, 2));
        float corr = __expf(m_i - mx);
        m_i = mx;
        float lsum = 0.0f;
        #pragma unroll
        for (int j = 0; j < 16; j++) {
            float p = __expf(s[j] - mx);
            s[j] = p;
            lsum += p;
        }
        lsum += __shfl_xor_sync(0xffffffffu, lsum, 1);
        lsum += __shfl_xor_sync(0xffffffffu, lsum, 2);
        l_i = l_i * corr + lsum;

        #pragma unroll
        for (int j = 0; j < 16; j++)
            Ps[r * SPAD + q4 + 4 * j] = s[j];
        #pragma unroll
        for (int j = 0; j < 16; j++) o[j] *= corr;
        __syncthreads();   // Ps complete (also fences Vs usage below vs loads above)

        // ---- O[r][d] += sum_c P[r][c] * V[c][d], d = 16*jj + 4*q4 + e
        #pragma unroll 8
        for (int c = 0; c < BC; c++) {
            float pv = Ps[r * SPAD + c];
            #pragma unroll
            for (int jj = 0; jj < 4; jj++) {
                float4 vv = *(const float4*)&Vs[c * SPAD + jj * 16 + q4 * 4];
                o[4 * jj + 0] = fmaf(pv, vv.x, o[4 * jj + 0]);
                o[4 * jj + 1] = fmaf(pv, vv.y, o[4 * jj + 1]);
                o[4 * jj + 2] = fmaf(pv, vv.z, o[4 * jj + 2]);
                o[4 * jj + 3] = fmaf(pv, vv.w, o[4 * jj + 3]);
            }
        }
    }

    // ---- normalize and write y[b, t, h*64 + d]
    float inv_l = 1.0f / l_i;
    float* ybase = y + (size_t)(b * T_SEQ + qt * BR + r) * C_EMB + h * HD;
    #pragma unroll
    for (int jj = 0; jj < 4; jj++) {
        float4 res;
        res.x = o[4 * jj + 0] * inv_l;
        res.y = o[4 * jj + 1] * inv_l;
        res.z = o[4 * jj + 2] * inv_l;
        res.w = o[4 * jj + 3] * inv_l;
        *(float4*)(ybase + jj * 16 + q4 * 4) = res;
    }
}

// ---------------------------------------------------------------------------
extern "C" void kernel_launch(void* const* d_in, const int* in_sizes, int n_in,
                              void* d_out, int out_size)
{
    const float* x      = (const float*)d_in[0];
    const float* W_attn = (const float*)d_in[1];
    const float* b_attn = (const float*)d_in[2];
    const float* W_proj = (const float*)d_in[3];
    const float* b_proj = (const float*)d_in[4];
    float* out = (float*)d_out;

    float *qkv, *yb;
    cudaGetSymbolAddress((void**)&qkv, g_qkv);
    cudaGetSymbolAddress((void**)&yb,  g_y);

    // 1) qkv = x @ W_attn + b_attn   [8192,1024]x[1024,3072]
    dim3 g1(C3 / 128, M_ROWS / 128);
    gemm_bias_kernel<<<g1, 256>>>(x, W_attn, b_attn, qkv, M_ROWS, C3, C_EMB);

    // 2) causal flash attention -> y [8192,1024]
    cudaFuncSetAttribute(attn_kernel,
                         cudaFuncAttributeMaxDynamicSharedMemorySize,
                         ATTN_SMEM_BYTES);
    attn_kernel<<<dim3(T_SEQ / BR, NH, BATCH), 256, ATTN_SMEM_BYTES>>>(qkv, yb);

    // 3) out = y @ W_proj + b_proj  [8192,1024]x[1024,1024]
    dim3 g2(C_EMB / 128, M_ROWS / 128);
    gemm_bias_kernel<<<g2, 256>>>(yb, W_proj, b_proj, out, M_ROWS, C_EMB, C_EMB);
}

// round 3
// speedup vs baseline: 1.4625x; 1.4625x over previous
#include <cuda_runtime.h>
#include <stdint.h>

#define BATCH 4
#define T_SEQ 2048
#define C_EMB 1024
#define NH 16
#define HD 64
#define C3 (3 * C_EMB)
#define M_ROWS (BATCH * T_SEQ)

// Scratch: __device__ globals (runtime allocation is forbidden).
__device__ float g_qkv[(size_t)M_ROWS * C3];     // [8192, 3072]
__device__ float g_y[(size_t)M_ROWS * C_EMB];    // [8192, 1024]

// ===========================================================================
// helpers
// ===========================================================================
__device__ __forceinline__ uint32_t smem_u32(const void* p) {
    uint32_t a;
    asm("{ .reg .u64 t; cvta.to.shared.u64 t, %1; cvt.u32.u64 %0, t; }"
        : "=r"(a) : "l"(p));
    return a;
}

__device__ __forceinline__ uint32_t f2tf32(float f) {
    uint32_t r;
    asm("cvt.rna.tf32.f32 %0, %1;" : "=r"(r) : "f"(f));
    return r;
}

#define CP_ASYNC16(dst_u32, src_ptr) \
    asm volatile("cp.async.cg.shared.global [%0], [%1], 16;" \
        :: "r"(dst_u32), "l"(src_ptr) : "memory")
#define CP_COMMIT() asm volatile("cp.async.commit_group;" ::: "memory")
#define CP_WAIT(n)  asm volatile("cp.async.wait_group %0;" :: "n"(n) : "memory")

__device__ __forceinline__ void mma_tf32(float* d, const uint32_t* a, const uint32_t* b) {
    asm volatile(
        "mma.sync.aligned.m16n8k8.row.col.f32.tf32.tf32.f32 "
        "{%0,%1,%2,%3}, {%4,%5,%6,%7}, {%8,%9}, {%0,%1,%2,%3};"
        : "+f"(d[0]), "+f"(d[1]), "+f"(d[2]), "+f"(d[3])
        : "r"(a[0]), "r"(a[1]), "r"(a[2]), "r"(a[3]), "r"(b[0]), "r"(b[1]));
}

// ===========================================================================
// TF32 mma.sync GEMM: C[M,N] = A[M,K] @ B[K,N] + bias[N]
// BM=BN=128, BK=32, 256 threads (8 warps: 4 along M x 2 along N).
// Warp tile 32x64: 2 M-tiles (m16) x 8 N-tiles (n8), k-steps of 8.
// SMEM: As[2][128][36] (row-major, pad 4), Bs[2][32][136] (k-major, pad 8).
//   A-frag LDS bank = lane (conflict-free); B-frag bank = 8*tg+g+8*nt (c-free).
// cp.async double-buffered; cvt.rna.tf32 applied at register load time
// (HW mma truncates raw fp32 -> ~1e-3 bias; RN pre-round makes it ~2e-4).
// ===========================================================================
#define BM 128
#define BN 128
#define BKT 32
#define A_STRIDE 36
#define B_STRIDE 136
#define A_BUF_FLOATS (BM * A_STRIDE)       // 4608
#define B_BUF_FLOATS (BKT * B_STRIDE)      // 4352
#define GEMM_SMEM_BYTES ((2 * A_BUF_FLOATS + 2 * B_BUF_FLOATS) * 4)  // 71680

__global__ __launch_bounds__(256) void gemm_tc_kernel(
    const float* __restrict__ A, const float* __restrict__ B,
    const float* __restrict__ bias, float* __restrict__ C,
    int M, int N, int K)
{
    extern __shared__ float sm[];
    float* As = sm;                                  // [2][BM][A_STRIDE]
    float* Bs = sm + 2 * A_BUF_FLOATS;               // [2][BKT][B_STRIDE]
    const uint32_t as_u32 = smem_u32(As);
    const uint32_t bs_u32 = smem_u32(Bs);

    const int tid  = threadIdx.x;
    const int wid  = tid >> 5;
    const int lane = tid & 31;
    const int g    = lane >> 2;      // group id 0..7
    const int tg   = lane & 3;       // thread-in-group 0..3
    const int warpM = (wid & 3) * 32;
    const int warpN = (wid >> 2) * 64;
    const int rowBase = blockIdx.y * BM;
    const int colBase = blockIdx.x * BN;
    const int NT = K / BKT;

    // ---- cp.async issue for one K-tile into buffer buf
    auto issue_tile = [&](int kt, int buf) {
        const float* Ap = A + (size_t)rowBase * K + kt * BKT;
        uint32_t adst = as_u32 + buf * A_BUF_FLOATS * 4;
        #pragma unroll
        for (int i = 0; i < 4; i++) {
            int f = tid + 256 * i;           // 0..1023 chunks
            int r = f >> 3, c = f & 7;       // row 0..127, 16B chunk 0..7
            CP_ASYNC16(adst + (uint32_t)(r * A_STRIDE + c * 4) * 4,
                       Ap + (size_t)r * K + c * 4);
        }
        const float* Bp = B + (size_t)(kt * BKT) * N + colBase;
        uint32_t bdst = bs_u32 + buf * B_BUF_FLOATS * 4;
        #pragma unroll
        for (int i = 0; i < 4; i++) {
            int f = tid + 256 * i;           // 0..1023 chunks
            int k = f >> 5, c = f & 31;      // k-row 0..31, chunk 0..31
            CP_ASYNC16(bdst + (uint32_t)(k * B_STRIDE + c * 4) * 4,
                       Bp + (size_t)k * N + c * 4);
        }
        CP_COMMIT();
    };

    float acc[2][8][4];
    #pragma unroll
    for (int mt = 0; mt < 2; mt++)
        #pragma unroll
        for (int nt = 0; nt < 8; nt++)
            #pragma unroll
            for (int e = 0; e < 4; e++) acc[mt][nt][e] = 0.0f;

    issue_tile(0, 0);
    issue_tile(1, 1);

    for (int kt = 0; kt < NT; kt++) {
        CP_WAIT(1);
        __syncthreads();

        const float* Ab = As + (kt & 1) * A_BUF_FLOATS;
        const float* Bb = Bs + (kt & 1) * B_BUF_FLOATS;

        #pragma unroll
        for (int s = 0; s < 4; s++) {        // k-steps of 8 within BK=32
            uint32_t af[2][4], bf[8][2];
            #pragma unroll
            for (int mt = 0; mt < 2; mt++) {
                const float* ap = Ab + (warpM + mt * 16 + g) * A_STRIDE + s * 8 + tg;
                af[mt][0] = f2tf32(ap[0]);
                af[mt][1] = f2tf32(ap[8 * A_STRIDE]);
                af[mt][2] = f2tf32(ap[4]);
                af[mt][3] = f2tf32(ap[8 * A_STRIDE + 4]);
            }
            #pragma unroll
            for (int nt = 0; nt < 8; nt++) {
                const float* bp = Bb + (s * 8 + tg) * B_STRIDE + warpN + nt * 8 + g;
                bf[nt][0] = f2tf32(bp[0]);
                bf[nt][1] = f2tf32(bp[4 * B_STRIDE]);
            }
            #pragma unroll
            for (int mt = 0; mt < 2; mt++)
                #pragma unroll
                for (int nt = 0; nt < 8; nt++)
                    mma_tf32(acc[mt][nt], af[mt], bf[nt]);
        }

        __syncthreads();
        if (kt + 2 < NT) issue_tile(kt + 2, kt & 1);
    }

    // ---- epilogue: direct STG.64 (+bias). Per c-pair, 4 lanes cover 32B.
    #pragma unroll
    for (int mt = 0; mt < 2; mt++) {
        #pragma unroll
        for (int nt = 0; nt < 8; nt++) {
            int col = colBase + warpN + nt * 8 + 2 * tg;
            float2 bb = *(const float2*)&bias[col];
            int row0 = rowBase + warpM + mt * 16 + g;
            float2 v0 = { acc[mt][nt][0] + bb.x, acc[mt][nt][1] + bb.y };
            float2 v1 = { acc[mt][nt][2] + bb.x, acc[mt][nt][3] + bb.y };
            *(float2*)&C[(size_t)row0 * N + col] = v0;
            *(float2*)&C[(size_t)(row0 + 8) * N + col] = v1;
        }
    }
}

// ===========================================================================
// Flash attention (causal), fp32 SIMT (unchanged from R1; tensorize later).
// ===========================================================================
#define BR 64
#define BC 64
#define SPAD 68
#define ATTN_SMEM_FLOATS (2 * BR * SPAD + 2 * BC * SPAD)
#define ATTN_SMEM_BYTES (ATTN_SMEM_FLOATS * 4)

__global__ __launch_bounds__(256) void attn_kernel(
    const float* __restrict__ qkv, float* __restrict__ y)
{
    extern __shared__ float smemf[];
    float* Qs = smemf;
    float* Ks = Qs + BR * SPAD;
    float* Vs = Ks + BC * SPAD;
    float* Ps = Vs + BC * SPAD;

    int qt = blockIdx.x;
    int h  = blockIdx.y;
    int b  = blockIdx.z;
    int tid = threadIdx.x;
    int r  = tid >> 2;
    int q4 = tid & 3;

    const float* qbase = qkv + (size_t)(b * T_SEQ + qt * BR) * C3 + h * HD;
    #pragma unroll
    for (int i = 0; i < 4; i++) {
        int idx = tid + 256 * i;
        int row = idx >> 4;
        int c4  = (idx & 15) << 2;
        *(float4*)&Qs[row * SPAD + c4] = *(const float4*)(qbase + (size_t)row * C3 + c4);
    }

    float m_i = -1e30f, l_i = 0.0f;
    float o[16];
    #pragma unroll
    for (int j = 0; j < 16; j++) o[j] = 0.0f;
    const float scale = 0.125f;

    for (int kt = 0; kt <= qt; kt++) {
        const float* kbase = qkv + (size_t)(b * T_SEQ + kt * BC) * C3 + C_EMB + h * HD;
        const float* vbase = kbase + C_EMB;

        __syncthreads();
        #pragma unroll
        for (int i = 0; i < 4; i++) {
            int idx = tid + 256 * i;
            int row = idx >> 4;
            int c4  = (idx & 15) << 2;
            *(float4*)&Ks[row * SPAD + c4] = *(const float4*)(kbase + (size_t)row * C3 + c4);
            *(float4*)&Vs[row * SPAD + c4] = *(const float4*)(vbase + (size_t)row * C3 + c4);
        }
        __syncthreads();

        float s[16];
        #pragma unroll
        for (int j = 0; j < 16; j++) s[j] = 0.0f;
        #pragma unroll 4
        for (int d4 = 0; d4 < 16; d4++) {
            float4 qv = *(const float4*)&Qs[r * SPAD + 4 * d4];
            #pragma unroll
            for (int j = 0; j < 16; j++) {
                float4 kv = *(const float4*)&Ks[(q4 + 4 * j) * SPAD + 4 * d4];
                s[j] = fmaf(qv.x, kv.x, fmaf(qv.y, kv.y,
                       fmaf(qv.z, kv.z, fmaf(qv.w, kv.w, s[j]))));
            }
        }

        bool diag = (kt == qt);
        float mx = m_i;
        #pragma unroll
        for (int j = 0; j < 16; j++) {
            int c = q4 + 4 * j;
            float v = s[j] * scale;
            if (diag && c > r) v = -1e30f;
            s[j] = v;
            mx = fmaxf(mx, v);
        }
        mx = fmaxf(mx, __shfl_xor_sync(0xffffffffu, mx, 1));
        mx = fmaxf(mx, __shfl_xor_sync(0xffffffffu, mx, 2));
        float corr = __expf(m_i - mx);
        m_i = mx;
        float lsum = 0.0f;
        #pragma unroll
        for (int j = 0; j < 16; j++) {
            float p = __expf(s[j] - mx);
            s[j] = p;
            lsum += p;
        }
        lsum += __shfl_xor_sync(0xffffffffu, lsum, 1);
        lsum += __shfl_xor_sync(0xffffffffu, lsum, 2);
        l_i = l_i * corr + lsum;

        #pragma unroll
        for (int j = 0; j < 16; j++)
            Ps[r * SPAD + q4 + 4 * j] = s[j];
        #pragma unroll
        for (int j = 0; j < 16; j++) o[j] *= corr;
        __syncthreads();

        #pragma unroll 8
        for (int c = 0; c < BC; c++) {
            float pv = Ps[r * SPAD + c];
            #pragma unroll
            for (int jj = 0; jj < 4; jj++) {
                float4 vv = *(const float4*)&Vs[c * SPAD + jj * 16 + q4 * 4];
                o[4 * jj + 0] = fmaf(pv, vv.x, o[4 * jj + 0]);
                o[4 * jj + 1] = fmaf(pv, vv.y, o[4 * jj + 1]);
                o[4 * jj + 2] = fmaf(pv, vv.z, o[4 * jj + 2]);
                o[4 * jj + 3] = fmaf(pv, vv.w, o[4 * jj + 3]);
            }
        }
    }

    float inv_l = 1.0f / l_i;
    float* ybase = y + (size_t)(b * T_SEQ + qt * BR + r) * C_EMB + h * HD;
    #pragma unroll
    for (int jj = 0; jj < 4; jj++) {
        float4 res;
        res.x = o[4 * jj + 0] * inv_l;
        res.y = o[4 * jj + 1] * inv_l;
        res.z = o[4 * jj + 2] * inv_l;
        res.w = o[4 * jj + 3] * inv_l;
        *(float4*)(ybase + jj * 16 + q4 * 4) = res;
    }
}

// ===========================================================================
extern "C" void kernel_launch(void* const* d_in, const int* in_sizes, int n_in,
                              void* d_out, int out_size)
{
    const float* x      = (const float*)d_in[0];
    const float* W_attn = (const float*)d_in[1];
    const float* b_attn = (const float*)d_in[2];
    const float* W_proj = (const float*)d_in[3];
    const float* b_proj = (const float*)d_in[4];
    float* out = (float*)d_out;

    float *qkv, *yb;
    cudaGetSymbolAddress((void**)&qkv, g_qkv);
    cudaGetSymbolAddress((void**)&yb,  g_y);

    cudaFuncSetAttribute(gemm_tc_kernel,
                         cudaFuncAttributeMaxDynamicSharedMemorySize, GEMM_SMEM_BYTES);
    cudaFuncSetAttribute(attn_kernel,
                         cudaFuncAttributeMaxDynamicSharedMemorySize, ATTN_SMEM_BYTES);

    // 1) qkv = x @ W_attn + b_attn   [8192,1024] x [1024,3072]
    gemm_tc_kernel<<<dim3(C3 / BN, M_ROWS / BM), 256, GEMM_SMEM_BYTES>>>(
        x, W_attn, b_attn, qkv, M_ROWS, C3, C_EMB);

    // 2) causal flash attention -> y [8192,1024]
    attn_kernel<<<dim3(T_SEQ / BR, NH, BATCH), 256, ATTN_SMEM_BYTES>>>(qkv, yb);

    // 3) out = y @ W_proj + b_proj  [8192,1024] x [1024,1024]
    gemm_tc_kernel<<<dim3(C_EMB / BN, M_ROWS / BM), 256, GEMM_SMEM_BYTES>>>(
        yb, W_proj, b_proj, out, M_ROWS, C_EMB, C_EMB);
}

// round 7
// speedup vs baseline: 4.0018x; 2.7363x over previous
#include <cuda_runtime.h>
#include <stdint.h>

#define BATCH 4
#define T_SEQ 2048
#define C_EMB 1024
#define NH 16
#define HD 64
#define C3 (3 * C_EMB)
#define M_ROWS (BATCH * T_SEQ)

// Scratch: __device__ globals (runtime allocation is forbidden).
__device__ float g_qkv[(size_t)M_ROWS * C3];     // [8192, 3072]
__device__ float g_y[(size_t)M_ROWS * C_EMB];    // [8192, 1024]

// ===========================================================================
// helpers
// ===========================================================================
__device__ __forceinline__ uint32_t smem_u32(const void* p) {
    uint32_t a;
    asm("{ .reg .u64 t; cvta.to.shared.u64 t, %1; cvt.u32.u64 %0, t; }"
        : "=r"(a) : "l"(p));
    return a;
}

__device__ __forceinline__ uint32_t f2tf32(float f) {
    uint32_t r;
    asm("cvt.rna.tf32.f32 %0, %1;" : "=r"(r) : "f"(f));
    return r;
}

#define CP_ASYNC16(dst_u32, src_ptr) \
    asm volatile("cp.async.cg.shared.global [%0], [%1], 16;" \
        :: "r"(dst_u32), "l"(src_ptr) : "memory")
#define CP_COMMIT() asm volatile("cp.async.commit_group;" ::: "memory")
#define CP_WAIT(n)  asm volatile("cp.async.wait_group %0;" :: "n"(n) : "memory")

__device__ __forceinline__ void mma_tf32(float* d, const uint32_t* a, const uint32_t* b) {
    asm volatile(
        "mma.sync.aligned.m16n8k8.row.col.f32.tf32.tf32.f32 "
        "{%0,%1,%2,%3}, {%4,%5,%6,%7}, {%8,%9}, {%0,%1,%2,%3};"
        : "+f"(d[0]), "+f"(d[1]), "+f"(d[2]), "+f"(d[3])
        : "r"(a[0]), "r"(a[1]), "r"(a[2]), "r"(a[3]), "r"(b[0]), "r"(b[1]));
}

// ===========================================================================
// TF32 mma.sync GEMM: C[M,N] = A[M,K] @ B[K,N] + bias[N]   (unchanged from R3)
// ===========================================================================
#define BM 128
#define BN 128
#define BKT 32
#define A_STRIDE 36
#define B_STRIDE 136
#define A_BUF_FLOATS (BM * A_STRIDE)
#define B_BUF_FLOATS (BKT * B_STRIDE)
#define GEMM_SMEM_BYTES ((2 * A_BUF_FLOATS + 2 * B_BUF_FLOATS) * 4)

__global__ __launch_bounds__(256) void gemm_tc_kernel(
    const float* __restrict__ A, const float* __restrict__ B,
    const float* __restrict__ bias, float* __restrict__ C,
    int M, int N, int K)
{
    extern __shared__ float sm[];
    float* As = sm;
    float* Bs = sm + 2 * A_BUF_FLOATS;
    const uint32_t as_u32 = smem_u32(As);
    const uint32_t bs_u32 = smem_u32(Bs);

    const int tid  = threadIdx.x;
    const int wid  = tid >> 5;
    const int lane = tid & 31;
    const int g    = lane >> 2;
    const int tg   = lane & 3;
    const int warpM = (wid & 3) * 32;
    const int warpN = (wid >> 2) * 64;
    const int rowBase = blockIdx.y * BM;
    const int colBase = blockIdx.x * BN;
    const int NT = K / BKT;

    auto issue_tile = [&](int kt, int buf) {
        const float* Ap = A + (size_t)rowBase * K + kt * BKT;
        uint32_t adst = as_u32 + buf * A_BUF_FLOATS * 4;
        #pragma unroll
        for (int i = 0; i < 4; i++) {
            int f = tid + 256 * i;
            int r = f >> 3, c = f & 7;
            CP_ASYNC16(adst + (uint32_t)(r * A_STRIDE + c * 4) * 4,
                       Ap + (size_t)r * K + c * 4);
        }
        const float* Bp = B + (size_t)(kt * BKT) * N + colBase;
        uint32_t bdst = bs_u32 + buf * B_BUF_FLOATS * 4;
        #pragma unroll
        for (int i = 0; i < 4; i++) {
            int f = tid + 256 * i;
            int k = f >> 5, c = f & 31;
            CP_ASYNC16(bdst + (uint32_t)(k * B_STRIDE + c * 4) * 4,
                       Bp + (size_t)k * N + c * 4);
        }
        CP_COMMIT();
    };

    float acc[2][8][4];
    #pragma unroll
    for (int mt = 0; mt < 2; mt++)
        #pragma unroll
        for (int nt = 0; nt < 8; nt++)
            #pragma unroll
            for (int e = 0; e < 4; e++) acc[mt][nt][e] = 0.0f;

    issue_tile(0, 0);
    issue_tile(1, 1);

    for (int kt = 0; kt < NT; kt++) {
        CP_WAIT(1);
        __syncthreads();

        const float* Ab = As + (kt & 1) * A_BUF_FLOATS;
        const float* Bb = Bs + (kt & 1) * B_BUF_FLOATS;

        #pragma unroll
        for (int s = 0; s < 4; s++) {
            uint32_t af[2][4], bf[8][2];
            #pragma unroll
            for (int mt = 0; mt < 2; mt++) {
                const float* ap = Ab + (warpM + mt * 16 + g) * A_STRIDE + s * 8 + tg;
                af[mt][0] = f2tf32(ap[0]);
                af[mt][1] = f2tf32(ap[8 * A_STRIDE]);
                af[mt][2] = f2tf32(ap[4]);
                af[mt][3] = f2tf32(ap[8 * A_STRIDE + 4]);
            }
            #pragma unroll
            for (int nt = 0; nt < 8; nt++) {
                const float* bp = Bb + (s * 8 + tg) * B_STRIDE + warpN + nt * 8 + g;
                bf[nt][0] = f2tf32(bp[0]);
                bf[nt][1] = f2tf32(bp[4 * B_STRIDE]);
            }
            #pragma unroll
            for (int mt = 0; mt < 2; mt++)
                #pragma unroll
                for (int nt = 0; nt < 8; nt++)
                    mma_tf32(acc[mt][nt], af[mt], bf[nt]);
        }

        __syncthreads();
        if (kt + 2 < NT) issue_tile(kt + 2, kt & 1);
    }

    #pragma unroll
    for (int mt = 0; mt < 2; mt++) {
        #pragma unroll
        for (int nt = 0; nt < 8; nt++) {
            int col = colBase + warpN + nt * 8 + 2 * tg;
            float2 bb = *(const float2*)&bias[col];
            int row0 = rowBase + warpM + mt * 16 + g;
            float2 v0 = { acc[mt][nt][0] + bb.x, acc[mt][nt][1] + bb.y };
            float2 v1 = { acc[mt][nt][2] + bb.x, acc[mt][nt][3] + bb.y };
            *(float2*)&C[(size_t)row0 * N + col] = v0;
            *(float2*)&C[(size_t)(row0 + 8) * N + col] = v1;
        }
    }
}

// ===========================================================================
// Flash attention (causal) on mma.sync TF32.
// BR=128 (8 warps x 16 q-rows), BC=64, D=64, 256 threads.
// Q: register-resident tf32 A-fragments (loaded once via smem staging).
// K,V: cp.async double-buffered smem tiles [64][68] (stride 68 -> K-frag and
//      P/Q A-frag LDS conflict-free; V-frag 2-way, acceptable).
// P: per-warp smem patch [16][68], written post-softmax, reread as A-frags.
// Online softmax entirely in registers (2 rows/thread, quad shfl for max,
// lane-partial l reduced once at the end).
// ===========================================================================
#define ABR 128
#define ABC 64
#define ASTR 68
#define AK0 0
#define AV0 (ABC * ASTR)            // 4352
#define AK1 (2 * ABC * ASTR)        // 8704
#define AV1 (3 * ABC * ASTR)        // 13056
#define APS (4 * ABC * ASTR)        // 17408
#define ATTN_SMEM_FLOATS (APS + 8 * 16 * ASTR)   // 26112
#define ATTN_SMEM_BYTES (ATTN_SMEM_FLOATS * 4)   // 104448

__global__ __launch_bounds__(256) void attn_tc_kernel(
    const float* __restrict__ qkv, float* __restrict__ y)
{
    extern __shared__ float sm[];
    const uint32_t sm32 = smem_u32(sm);

    const int qt = (gridDim.x - 1) - blockIdx.x;   // big tiles first (balance)
    const int h  = blockIdx.y;
    const int b  = blockIdx.z;
    const int tid  = threadIdx.x;
    const int wid  = tid >> 5;
    const int lane = tid & 31;
    const int g    = lane >> 2;
    const int tg   = lane & 3;
    const int qrow0 = qt * ABR;
    const int rw    = wid * 16;
    float* Pw = sm + APS + wid * (16 * ASTR);

    // ---- stage Q (coalesced) into P region, read tf32 A-fragments
    {
        const float* qg = qkv + (size_t)(b * T_SEQ + qrow0) * C3 + h * HD;
        #pragma unroll
        for (int i = 0; i < 8; i++) {
            int f = tid + 256 * i;             // 0..2047 float4s
            int row = f >> 4;
            int c4  = (f & 15) << 2;
            *(float4*)&sm[APS + (row >> 4) * (16 * ASTR) + (row & 15) * ASTR + c4] =
                *(const float4*)(qg + (size_t)row * C3 + c4);
        }
    }
    __syncthreads();
    uint32_t qf[8][4];
    #pragma unroll
    for (int s = 0; s < 8; s++) {
        const float* qp = Pw + g * ASTR + s * 8 + tg;
        qf[s][0] = f2tf32(qp[0]);
        qf[s][1] = f2tf32(qp[8 * ASTR]);
        qf[s][2] = f2tf32(qp[4]);
        qf[s][3] = f2tf32(qp[8 * ASTR + 4]);
    }
    // Pw is private to this warp from here on; warp-local sync suffices later.

    float o[8][4];
    #pragma unroll
    for (int nt = 0; nt < 8; nt++)
        #pragma unroll
        for (int e = 0; e < 4; e++) o[nt][e] = 0.0f;
    float m0 = -1e30f, m1 = -1e30f, l0 = 0.0f, l1 = 0.0f;
    const float scale = 0.125f;

    const int KT = 2 * qt + 2;

    auto issue = [&](int kt, int buf) {
        const float* kb = qkv + (size_t)(b * T_SEQ + kt * ABC) * C3 + C_EMB + h * HD;
        const float* vb = kb + C_EMB;
        uint32_t kdst = sm32 + (buf ? AK1 : AK0) * 4;
        uint32_t vdst = sm32 + (buf ? AV1 : AV0) * 4;
        #pragma unroll
        for (int i = 0; i < 4; i++) {
            int f = tid + 256 * i;             // 0..1023 chunks
            int row = f >> 4, c = f & 15;
            CP_ASYNC16(kdst + (uint32_t)(row * ASTR + c * 4) * 4,
                       kb + (size_t)row * C3 + c * 4);
        }
        #pragma unroll
        for (int i = 0; i < 4; i++) {
            int f = tid + 256 * i;
            int row = f >> 4, c = f & 15;
            CP_ASYNC16(vdst + (uint32_t)(row * ASTR + c * 4) * 4,
                       vb + (size_t)row * C3 + c * 4);
        }
        CP_COMMIT();
    };

    issue(0, 0);
    for (int kt = 0; kt < KT; kt++) {
        if (kt + 1 < KT) { issue(kt + 1, (kt + 1) & 1); CP_WAIT(1); }
        else             { CP_WAIT(0); }
        __syncthreads();

        const float* Kb = sm + ((kt & 1) ? AK1 : AK0);
        const float* Vb = sm + ((kt & 1) ? AV1 : AV0);

        // warp-uniform: skip fully-masked diagonal-band tiles
        bool alive = (kt * ABC) <= (qrow0 + rw + 15);
        if (alive) {
            // ---- S = Q K^T  (16x64 per warp)
            float sa[8][4];
            #pragma unroll
            for (int nt = 0; nt < 8; nt++)
                #pragma unroll
                for (int e = 0; e < 4; e++) sa[nt][e] = 0.0f;
            #pragma unroll
            for (int s = 0; s < 8; s++) {
                #pragma unroll
                for (int nt = 0; nt < 8; nt++) {
                    uint32_t bf[2];
                    const float* kp = Kb + (nt * 8 + g) * ASTR + s * 8 + tg;
                    bf[0] = f2tf32(kp[0]);
                    bf[1] = f2tf32(kp[4]);
                    mma_tf32(sa[nt], qf[s], bf);
                }
            }

            // ---- mask + online softmax
            bool band = (kt * ABC + ABC - 1) > (qrow0 + rw);
            int grow0 = qrow0 + rw + g;
            int gcol0 = kt * ABC + 2 * tg;
            float mx0 = m0, mx1 = m1;
            #pragma unroll
            for (int nt = 0; nt < 8; nt++) {
                int c0 = gcol0 + nt * 8;
                float v0 = sa[nt][0] * scale;
                float v1 = sa[nt][1] * scale;
                float v2 = sa[nt][2] * scale;
                float v3 = sa[nt][3] * scale;
                if (band) {
                    if (c0     > grow0)     v0 = -1e30f;
                    if (c0 + 1 > grow0)     v1 = -1e30f;
                    if (c0     > grow0 + 8) v2 = -1e30f;
                    if (c0 + 1 > grow0 + 8) v3 = -1e30f;
                }
                sa[nt][0] = v0; sa[nt][1] = v1; sa[nt][2] = v2; sa[nt][3] = v3;
                mx0 = fmaxf(mx0, fmaxf(v0, v1));
                mx1 = fmaxf(mx1, fmaxf(v2, v3));
            }
            mx0 = fmaxf(mx0, __shfl_xor_sync(0xffffffffu, mx0, 1));
            mx0 = fmaxf(mx0, __shfl_xor_sync(0xffffffffu, mx0, 2));
            mx1 = fmaxf(mx1, __shfl_xor_sync(0xffffffffu, mx1, 1));
            mx1 = fmaxf(mx1, __shfl_xor_sync(0xffffffffu, mx1, 2));
            float corr0 = __expf(m0 - mx0);
            float corr1 = __expf(m1 - mx1);
            m0 = mx0; m1 = mx1;

            float ls0 = 0.0f, ls1 = 0.0f;
            #pragma unroll
            for (int nt = 0; nt < 8; nt++) {
                float p0 = __expf(sa[nt][0] - m0);
                float p1 = __expf(sa[nt][1] - m0);
                float p2 = __expf(sa[nt][2] - m1);
                float p3 = __expf(sa[nt][3] - m1);
                sa[nt][0] = p0; sa[nt][1] = p1; sa[nt][2] = p2; sa[nt][3] = p3;
                ls0 += p0 + p1;
                ls1 += p2 + p3;
            }
            l0 = l0 * corr0 + ls0;       // lane-partial; reduced at the end
            l1 = l1 * corr1 + ls1;
            #pragma unroll
            for (int nt = 0; nt < 8; nt++) {
                o[nt][0] *= corr0; o[nt][1] *= corr0;
                o[nt][2] *= corr1; o[nt][3] *= corr1;
            }

            // ---- P -> smem (warp-private), reread as A-fragments
            __syncwarp();                 // prior PV reads of Pw done
            #pragma unroll
            for (int nt = 0; nt < 8; nt++) {
                *(float2*)&Pw[g * ASTR + nt * 8 + 2 * tg]       = *(float2*)&sa[nt][0];
                *(float2*)&Pw[(g + 8) * ASTR + nt * 8 + 2 * tg] = *(float2*)&sa[nt][2];
            }
            __syncwarp();

            // ---- O += P V
            #pragma unroll
            for (int s = 0; s < 8; s++) {
                uint32_t pf[4];
                const float* pp = Pw + g * ASTR + s * 8 + tg;
                pf[0] = f2tf32(pp[0]);
                pf[1] = f2tf32(pp[8 * ASTR]);
                pf[2] = f2tf32(pp[4]);
                pf[3] = f2tf32(pp[8 * ASTR + 4]);
                #pragma unroll
                for (int nt = 0; nt < 8; nt++) {
                    uint32_t bf[2];
                    const float* vp = Vb + (s * 8 + tg) * ASTR + nt * 8 + g;
                    bf[0] = f2tf32(vp[0]);
                    bf[1] = f2tf32(vp[4 * ASTR]);
                    mma_tf32(o[nt], pf, bf);
                }
            }
        }
        __syncthreads();   // everyone done with K/V buffer before reuse
    }

    // ---- final l reduction + normalize + write
    l0 += __shfl_xor_sync(0xffffffffu, l0, 1);
    l0 += __shfl_xor_sync(0xffffffffu, l0, 2);
    l1 += __shfl_xor_sync(0xffffffffu, l1, 1);
    l1 += __shfl_xor_sync(0xffffffffu, l1, 2);
    float inv0 = 1.0f / l0;
    float inv1 = 1.0f / l1;

    int row0 = b * T_SEQ + qrow0 + rw + g;
    #pragma unroll
    for (int nt = 0; nt < 8; nt++) {
        int col = h * HD + nt * 8 + 2 * tg;
        float2 v0 = { o[nt][0] * inv0, o[nt][1] * inv0 };
        float2 v1 = { o[nt][2] * inv1, o[nt][3] * inv1 };
        *(float2*)&y[(size_t)row0 * C_EMB + col] = v0;
        *(float2*)&y[(size_t)(row0 + 8) * C_EMB + col] = v1;
    }
}

// ===========================================================================
extern "C" void kernel_launch(void* const* d_in, const int* in_sizes, int n_in,
                              void* d_out, int out_size)
{
    const float* x      = (const float*)d_in[0];
    const float* W_attn = (const float*)d_in[1];
    const float* b_attn = (const float*)d_in[2];
    const float* W_proj = (const float*)d_in[3];
    const float* b_proj = (const float*)d_in[4];
    float* out = (float*)d_out;

    float *qkv, *yb;
    cudaGetSymbolAddress((void**)&qkv, g_qkv);
    cudaGetSymbolAddress((void**)&yb,  g_y);

    cudaFuncSetAttribute(gemm_tc_kernel,
                         cudaFuncAttributeMaxDynamicSharedMemorySize, GEMM_SMEM_BYTES);
    cudaFuncSetAttribute(attn_tc_kernel,
                         cudaFuncAttributeMaxDynamicSharedMemorySize, ATTN_SMEM_BYTES);

    // 1) qkv = x @ W_attn + b_attn   [8192,1024] x [1024,3072]
    gemm_tc_kernel<<<dim3(C3 / BN, M_ROWS / BM), 256, GEMM_SMEM_BYTES>>>(
        x, W_attn, b_attn, qkv, M_ROWS, C3, C_EMB);

    // 2) causal flash attention -> y [8192,1024]
    attn_tc_kernel<<<dim3(T_SEQ / ABR, NH, BATCH), 256, ATTN_SMEM_BYTES>>>(qkv, yb);

    // 3) out = y @ W_proj + b_proj  [8192,1024] x [1024,1024]
    gemm_tc_kernel<<<dim3(C_EMB / BN, M_ROWS / BM), 256, GEMM_SMEM_BYTES>>>(
        yb, W_proj, b_proj, out, M_ROWS, C_EMB, C_EMB);
}

// round 8
// speedup vs baseline: 4.4337x; 1.1079x over previous
#include <cuda_runtime.h>
#include <stdint.h>

#define BATCH 4
#define T_SEQ 2048
#define C_EMB 1024
#define NH 16
#define HD 64
#define C3 (3 * C_EMB)
#define M_ROWS (BATCH * T_SEQ)

// Scratch: __device__ globals (runtime allocation is forbidden).
__device__ float g_qkv[(size_t)M_ROWS * C3];     // [8192, 3072] (tf32-rounded)
__device__ float g_y[(size_t)M_ROWS * C_EMB];    // [8192, 1024] (tf32-rounded)
__device__ float g_xr[(size_t)M_ROWS * C_EMB];   // rounded x
__device__ float g_war[(size_t)C_EMB * C3];      // rounded W_attn
__device__ float g_wpr[(size_t)C_EMB * C_EMB];   // rounded W_proj

// ===========================================================================
// helpers
// ===========================================================================
__device__ __forceinline__ uint32_t smem_u32(const void* p) {
    uint32_t a;
    asm("{ .reg .u64 t; cvta.to.shared.u64 t, %1; cvt.u32.u64 %0, t; }"
        : "=r"(a) : "l"(p));
    return a;
}

__device__ __forceinline__ uint32_t f2tf32(float f) {
    uint32_t r;
    asm("cvt.rna.tf32.f32 %0, %1;" : "=r"(r) : "f"(f));
    return r;
}

#define CP_ASYNC16(dst_u32, src_ptr) \
    asm volatile("cp.async.cg.shared.global [%0], [%1], 16;" \
        :: "r"(dst_u32), "l"(src_ptr) : "memory")
#define CP_COMMIT() asm volatile("cp.async.commit_group;" ::: "memory")
#define CP_WAIT(n)  asm volatile("cp.async.wait_group %0;" :: "n"(n) : "memory")

__device__ __forceinline__ void mma_tf32(float* d, const uint32_t* a, const uint32_t* b) {
    asm volatile(
        "mma.sync.aligned.m16n8k8.row.col.f32.tf32.tf32.f32 "
        "{%0,%1,%2,%3}, {%4,%5,%6,%7}, {%8,%9}, {%0,%1,%2,%3};"
        : "+f"(d[0]), "+f"(d[1]), "+f"(d[2]), "+f"(d[3])
        : "r"(a[0]), "r"(a[1]), "r"(a[2]), "r"(a[3]), "r"(b[0]), "r"(b[1]));
}

// ===========================================================================
// tf32 pre-round pass: dst[i] = round_rna_tf32(src[i]); float4 grid-stride.
// ===========================================================================
__global__ __launch_bounds__(256) void round_tf32_kernel(
    const float4* __restrict__ src, float4* __restrict__ dst, int n4)
{
    int i = blockIdx.x * blockDim.x + threadIdx.x;
    if (i < n4) {
        float4 v = src[i];
        float4 r;
        r.x = __uint_as_float(f2tf32(v.x));
        r.y = __uint_as_float(f2tf32(v.y));
        r.z = __uint_as_float(f2tf32(v.z));
        r.w = __uint_as_float(f2tf32(v.w));
        dst[i] = r;
    }
}

// ===========================================================================
// TF32 mma.sync GEMM: C[M,N] = A[M,K] @ B[K,N] + bias[N]
// Operands A,B must be PRE-ROUNDED to tf32 (mainloop has zero CVT).
// roundOut: epilogue rounds C to tf32 (for outputs feeding later tf32 stages).
// ===========================================================================
#define BM 128
#define BN 128
#define BKT 32
#define A_STRIDE 36
#define B_STRIDE 136
#define A_BUF_FLOATS (BM * A_STRIDE)
#define B_BUF_FLOATS (BKT * B_STRIDE)
#define GEMM_SMEM_BYTES ((2 * A_BUF_FLOATS + 2 * B_BUF_FLOATS) * 4)

__global__ __launch_bounds__(256) void gemm_tc_kernel(
    const float* __restrict__ A, const float* __restrict__ B,
    const float* __restrict__ bias, float* __restrict__ C,
    int M, int N, int K, int roundOut)
{
    extern __shared__ float sm[];
    float* As = sm;
    float* Bs = sm + 2 * A_BUF_FLOATS;
    const uint32_t as_u32 = smem_u32(As);
    const uint32_t bs_u32 = smem_u32(Bs);

    const int tid  = threadIdx.x;
    const int wid  = tid >> 5;
    const int lane = tid & 31;
    const int g    = lane >> 2;
    const int tg   = lane & 3;
    const int warpM = (wid & 3) * 32;
    const int warpN = (wid >> 2) * 64;
    const int rowBase = blockIdx.y * BM;
    const int colBase = blockIdx.x * BN;
    const int NT = K / BKT;

    auto issue_tile = [&](int kt, int buf) {
        const float* Ap = A + (size_t)rowBase * K + kt * BKT;
        uint32_t adst = as_u32 + buf * A_BUF_FLOATS * 4;
        #pragma unroll
        for (int i = 0; i < 4; i++) {
            int f = tid + 256 * i;
            int r = f >> 3, c = f & 7;
            CP_ASYNC16(adst + (uint32_t)(r * A_STRIDE + c * 4) * 4,
                       Ap + (size_t)r * K + c * 4);
        }
        const float* Bp = B + (size_t)(kt * BKT) * N + colBase;
        uint32_t bdst = bs_u32 + buf * B_BUF_FLOATS * 4;
        #pragma unroll
        for (int i = 0; i < 4; i++) {
            int f = tid + 256 * i;
            int k = f >> 5, c = f & 31;
            CP_ASYNC16(bdst + (uint32_t)(k * B_STRIDE + c * 4) * 4,
                       Bp + (size_t)k * N + c * 4);
        }
        CP_COMMIT();
    };

    float acc[2][8][4];
    #pragma unroll
    for (int mt = 0; mt < 2; mt++)
        #pragma unroll
        for (int nt = 0; nt < 8; nt++)
            #pragma unroll
            for (int e = 0; e < 4; e++) acc[mt][nt][e] = 0.0f;

    issue_tile(0, 0);
    issue_tile(1, 1);

    for (int kt = 0; kt < NT; kt++) {
        CP_WAIT(1);
        __syncthreads();

        const uint32_t* Ab = (const uint32_t*)(As + (kt & 1) * A_BUF_FLOATS);
        const uint32_t* Bb = (const uint32_t*)(Bs + (kt & 1) * B_BUF_FLOATS);

        #pragma unroll
        for (int s = 0; s < 4; s++) {
            uint32_t af[2][4], bf[8][2];
            #pragma unroll
            for (int mt = 0; mt < 2; mt++) {
                const uint32_t* ap = Ab + (warpM + mt * 16 + g) * A_STRIDE + s * 8 + tg;
                af[mt][0] = ap[0];
                af[mt][1] = ap[8 * A_STRIDE];
                af[mt][2] = ap[4];
                af[mt][3] = ap[8 * A_STRIDE + 4];
            }
            #pragma unroll
            for (int nt = 0; nt < 8; nt++) {
                const uint32_t* bp = Bb + (s * 8 + tg) * B_STRIDE + warpN + nt * 8 + g;
                bf[nt][0] = bp[0];
                bf[nt][1] = bp[4 * B_STRIDE];
            }
            #pragma unroll
            for (int mt = 0; mt < 2; mt++)
                #pragma unroll
                for (int nt = 0; nt < 8; nt++)
                    mma_tf32(acc[mt][nt], af[mt], bf[nt]);
        }

        __syncthreads();
        if (kt + 2 < NT) issue_tile(kt + 2, kt & 1);
    }

    #pragma unroll
    for (int mt = 0; mt < 2; mt++) {
        #pragma unroll
        for (int nt = 0; nt < 8; nt++) {
            int col = colBase + warpN + nt * 8 + 2 * tg;
            float2 bb = *(const float2*)&bias[col];
            int row0 = rowBase + warpM + mt * 16 + g;
            float2 v0 = { acc[mt][nt][0] + bb.x, acc[mt][nt][1] + bb.y };
            float2 v1 = { acc[mt][nt][2] + bb.x, acc[mt][nt][3] + bb.y };
            if (roundOut) {
                v0.x = __uint_as_float(f2tf32(v0.x));
                v0.y = __uint_as_float(f2tf32(v0.y));
                v1.x = __uint_as_float(f2tf32(v1.x));
                v1.y = __uint_as_float(f2tf32(v1.y));
            }
            *(float2*)&C[(size_t)row0 * N + col] = v0;
            *(float2*)&C[(size_t)(row0 + 8) * N + col] = v1;
        }
    }
}

// ===========================================================================
// Flash attention (causal) on mma.sync TF32. qkv is PRE-ROUNDED, so Q/K/V
// fragments load raw bits; only P (softmax output) needs CVT. Output y is
// written tf32-rounded for the proj GEMM.
// ===========================================================================
#define ABR 128
#define ABC 64
#define ASTR 68
#define AK0 0
#define AV0 (ABC * ASTR)
#define AK1 (2 * ABC * ASTR)
#define AV1 (3 * ABC * ASTR)
#define APS (4 * ABC * ASTR)
#define ATTN_SMEM_FLOATS (APS + 8 * 16 * ASTR)
#define ATTN_SMEM_BYTES (ATTN_SMEM_FLOATS * 4)

__global__ __launch_bounds__(256) void attn_tc_kernel(
    const float* __restrict__ qkv, float* __restrict__ y)
{
    extern __shared__ float sm[];
    const uint32_t sm32 = smem_u32(sm);

    const int qt = (gridDim.x - 1) - blockIdx.x;
    const int h  = blockIdx.y;
    const int b  = blockIdx.z;
    const int tid  = threadIdx.x;
    const int wid  = tid >> 5;
    const int lane = tid & 31;
    const int g    = lane >> 2;
    const int tg   = lane & 3;
    const int qrow0 = qt * ABR;
    const int rw    = wid * 16;
    float* Pw = sm + APS + wid * (16 * ASTR);

    // ---- stage Q (coalesced) into P region, read A-fragments (pre-rounded)
    {
        const float* qg = qkv + (size_t)(b * T_SEQ + qrow0) * C3 + h * HD;
        #pragma unroll
        for (int i = 0; i < 8; i++) {
            int f = tid + 256 * i;
            int row = f >> 4;
            int c4  = (f & 15) << 2;
            *(float4*)&sm[APS + (row >> 4) * (16 * ASTR) + (row & 15) * ASTR + c4] =
                *(const float4*)(qg + (size_t)row * C3 + c4);
        }
    }
    __syncthreads();
    uint32_t qf[8][4];
    #pragma unroll
    for (int s = 0; s < 8; s++) {
        const uint32_t* qp = (const uint32_t*)(Pw + g * ASTR + s * 8 + tg);
        qf[s][0] = qp[0];
        qf[s][1] = qp[8 * ASTR];
        qf[s][2] = qp[4];
        qf[s][3] = qp[8 * ASTR + 4];
    }

    float o[8][4];
    #pragma unroll
    for (int nt = 0; nt < 8; nt++)
        #pragma unroll
        for (int e = 0; e < 4; e++) o[nt][e] = 0.0f;
    float m0 = -1e30f, m1 = -1e30f, l0 = 0.0f, l1 = 0.0f;
    const float scale = 0.125f;

    const int KT = 2 * qt + 2;

    auto issue = [&](int kt, int buf) {
        const float* kb = qkv + (size_t)(b * T_SEQ + kt * ABC) * C3 + C_EMB + h * HD;
        const float* vb = kb + C_EMB;
        uint32_t kdst = sm32 + (buf ? AK1 : AK0) * 4;
        uint32_t vdst = sm32 + (buf ? AV1 : AV0) * 4;
        #pragma unroll
        for (int i = 0; i < 4; i++) {
            int f = tid + 256 * i;
            int row = f >> 4, c = f & 15;
            CP_ASYNC16(kdst + (uint32_t)(row * ASTR + c * 4) * 4,
                       kb + (size_t)row * C3 + c * 4);
        }
        #pragma unroll
        for (int i = 0; i < 4; i++) {
            int f = tid + 256 * i;
            int row = f >> 4, c = f & 15;
            CP_ASYNC16(vdst + (uint32_t)(row * ASTR + c * 4) * 4,
                       vb + (size_t)row * C3 + c * 4);
        }
        CP_COMMIT();
    };

    issue(0, 0);
    for (int kt = 0; kt < KT; kt++) {
        if (kt + 1 < KT) { issue(kt + 1, (kt + 1) & 1); CP_WAIT(1); }
        else             { CP_WAIT(0); }
        __syncthreads();

        const uint32_t* Kb = (const uint32_t*)(sm + ((kt & 1) ? AK1 : AK0));
        const uint32_t* Vb = (const uint32_t*)(sm + ((kt & 1) ? AV1 : AV0));

        bool alive = (kt * ABC) <= (qrow0 + rw + 15);
        if (alive) {
            // ---- S = Q K^T
            float sa[8][4];
            #pragma unroll
            for (int nt = 0; nt < 8; nt++)
                #pragma unroll
                for (int e = 0; e < 4; e++) sa[nt][e] = 0.0f;
            #pragma unroll
            for (int s = 0; s < 8; s++) {
                #pragma unroll
                for (int nt = 0; nt < 8; nt++) {
                    uint32_t bf[2];
                    const uint32_t* kp = Kb + (nt * 8 + g) * ASTR + s * 8 + tg;
                    bf[0] = kp[0];
                    bf[1] = kp[4];
                    mma_tf32(sa[nt], qf[s], bf);
                }
            }

            // ---- mask + online softmax
            bool band = (kt * ABC + ABC - 1) > (qrow0 + rw);
            int grow0 = qrow0 + rw + g;
            int gcol0 = kt * ABC + 2 * tg;
            float mx0 = m0, mx1 = m1;
            #pragma unroll
            for (int nt = 0; nt < 8; nt++) {
                int c0 = gcol0 + nt * 8;
                float v0 = sa[nt][0] * scale;
                float v1 = sa[nt][1] * scale;
                float v2 = sa[nt][2] * scale;
                float v3 = sa[nt][3] * scale;
                if (band) {
                    if (c0     > grow0)     v0 = -1e30f;
                    if (c0 + 1 > grow0)     v1 = -1e30f;
                    if (c0     > grow0 + 8) v2 = -1e30f;
                    if (c0 + 1 > grow0 + 8) v3 = -1e30f;
                }
                sa[nt][0] = v0; sa[nt][1] = v1; sa[nt][2] = v2; sa[nt][3] = v3;
                mx0 = fmaxf(mx0, fmaxf(v0, v1));
                mx1 = fmaxf(mx1, fmaxf(v2, v3));
            }
            mx0 = fmaxf(mx0, __shfl_xor_sync(0xffffffffu, mx0, 1));
            mx0 = fmaxf(mx0, __shfl_xor_sync(0xffffffffu, mx0, 2));
            mx1 = fmaxf(mx1, __shfl_xor_sync(0xffffffffu, mx1, 1));
            mx1 = fmaxf(mx1, __shfl_xor_sync(0xffffffffu, mx1, 2));
            float corr0 = __expf(m0 - mx0);
            float corr1 = __expf(m1 - mx1);
            m0 = mx0; m1 = mx1;

            float ls0 = 0.0f, ls1 = 0.0f;
            #pragma unroll
            for (int nt = 0; nt < 8; nt++) {
                float p0 = __expf(sa[nt][0] - m0);
                float p1 = __expf(sa[nt][1] - m0);
                float p2 = __expf(sa[nt][2] - m1);
                float p3 = __expf(sa[nt][3] - m1);
                sa[nt][0] = p0; sa[nt][1] = p1; sa[nt][2] = p2; sa[nt][3] = p3;
                ls0 += p0 + p1;
                ls1 += p2 + p3;
            }
            l0 = l0 * corr0 + ls0;
            l1 = l1 * corr1 + ls1;
            #pragma unroll
            for (int nt = 0; nt < 8; nt++) {
                o[nt][0] *= corr0; o[nt][1] *= corr0;
                o[nt][2] *= corr1; o[nt][3] *= corr1;
            }

            // ---- P -> smem (warp-private), reread as A-fragments (CVT here)
            __syncwarp();
            #pragma unroll
            for (int nt = 0; nt < 8; nt++) {
                *(float2*)&Pw[g * ASTR + nt * 8 + 2 * tg]       = *(float2*)&sa[nt][0];
                *(float2*)&Pw[(g + 8) * ASTR + nt * 8 + 2 * tg] = *(float2*)&sa[nt][2];
            }
            __syncwarp();

            // ---- O += P V
            #pragma unroll
            for (int s = 0; s < 8; s++) {
                uint32_t pf[4];
                const float* pp = Pw + g * ASTR + s * 8 + tg;
                pf[0] = f2tf32(pp[0]);
                pf[1] = f2tf32(pp[8 * ASTR]);
                pf[2] = f2tf32(pp[4]);
                pf[3] = f2tf32(pp[8 * ASTR + 4]);
                #pragma unroll
                for (int nt = 0; nt < 8; nt++) {
                    uint32_t bf[2];
                    const uint32_t* vp = Vb + (s * 8 + tg) * ASTR + nt * 8 + g;
                    bf[0] = vp[0];
                    bf[1] = vp[4 * ASTR];
                    mma_tf32(o[nt], pf, bf);
                }
            }
        }
        __syncthreads();
    }

    // ---- final l reduction + normalize + write (tf32-rounded for proj GEMM)
    l0 += __shfl_xor_sync(0xffffffffu, l0, 1);
    l0 += __shfl_xor_sync(0xffffffffu, l0, 2);
    l1 += __shfl_xor_sync(0xffffffffu, l1, 1);
    l1 += __shfl_xor_sync(0xffffffffu, l1, 2);
    float inv0 = 1.0f / l0;
    float inv1 = 1.0f / l1;

    int row0 = b * T_SEQ + qrow0 + rw + g;
    #pragma unroll
    for (int nt = 0; nt < 8; nt++) {
        int col = h * HD + nt * 8 + 2 * tg;
        float2 v0 = { __uint_as_float(f2tf32(o[nt][0] * inv0)),
                      __uint_as_float(f2tf32(o[nt][1] * inv0)) };
        float2 v1 = { __uint_as_float(f2tf32(o[nt][2] * inv1)),
                      __uint_as_float(f2tf32(o[nt][3] * inv1)) };
        *(float2*)&y[(size_t)row0 * C_EMB + col] = v0;
        *(float2*)&y[(size_t)(row0 + 8) * C_EMB + col] = v1;
    }
}

// ===========================================================================
extern "C" void kernel_launch(void* const* d_in, const int* in_sizes, int n_in,
                              void* d_out, int out_size)
{
    const float* x      = (const float*)d_in[0];
    const float* W_attn = (const float*)d_in[1];
    const float* b_attn = (const float*)d_in[2];
    const float* W_proj = (const float*)d_in[3];
    const float* b_proj = (const float*)d_in[4];
    float* out = (float*)d_out;

    float *qkv, *yb, *xr, *war, *wpr;
    cudaGetSymbolAddress((void**)&qkv, g_qkv);
    cudaGetSymbolAddress((void**)&yb,  g_y);
    cudaGetSymbolAddress((void**)&xr,  g_xr);
    cudaGetSymbolAddress((void**)&war, g_war);
    cudaGetSymbolAddress((void**)&wpr, g_wpr);

    cudaFuncSetAttribute(gemm_tc_kernel,
                         cudaFuncAttributeMaxDynamicSharedMemorySize, GEMM_SMEM_BYTES);
    cudaFuncSetAttribute(attn_tc_kernel,
                         cudaFuncAttributeMaxDynamicSharedMemorySize, ATTN_SMEM_BYTES);

    // 0) pre-round inputs to tf32 (once; hot loops then run CVT-free)
    {
        int n4x = (M_ROWS * C_EMB) / 4;          // 2097152
        int n4a = (C_EMB * C3) / 4;              // 786432
        int n4p = (C_EMB * C_EMB) / 4;           // 262144
        round_tf32_kernel<<<n4x / 256, 256>>>((const float4*)x, (float4*)xr, n4x);
        round_tf32_kernel<<<n4a / 256, 256>>>((const float4*)W_attn, (float4*)war, n4a);
        round_tf32_kernel<<<n4p / 256, 256>>>((const float4*)W_proj, (float4*)wpr, n4p);
    }

    // 1) qkv = x_r @ Wa_r + b_attn  (epilogue writes tf32-rounded qkv)
    gemm_tc_kernel<<<dim3(C3 / BN, M_ROWS / BM), 256, GEMM_SMEM_BYTES>>>(
        xr, war, b_attn, qkv, M_ROWS, C3, C_EMB, 1);

    // 2) causal flash attention -> y (tf32-rounded)
    attn_tc_kernel<<<dim3(T_SEQ / ABR, NH, BATCH), 256, ATTN_SMEM_BYTES>>>(qkv, yb);

    // 3) out = y @ Wp_r + b_proj  (final output: NOT rounded)
    gemm_tc_kernel<<<dim3(C_EMB / BN, M_ROWS / BM), 256, GEMM_SMEM_BYTES>>>(
        yb, wpr, b_proj, out, M_ROWS, C_EMB, C_EMB, 0);
}

// round 9
// speedup vs baseline: 4.6587x; 1.0507x over previous
#include <cuda_runtime.h>
#include <stdint.h>

#define BATCH 4
#define T_SEQ 2048
#define C_EMB 1024
#define NH 16
#define HD 64
#define C3 (3 * C_EMB)
#define M_ROWS (BATCH * T_SEQ)

// Scratch: __device__ globals (runtime allocation is forbidden).
__device__ float g_qkv[(size_t)M_ROWS * C3];     // [8192, 3072] (tf32-rounded)
__device__ float g_y[(size_t)M_ROWS * C_EMB];    // [8192, 1024] (tf32-rounded)
__device__ float g_xr[(size_t)M_ROWS * C_EMB];   // rounded x
__device__ float g_war[(size_t)C_EMB * C3];      // rounded W_attn
__device__ float g_wpr[(size_t)C_EMB * C_EMB];   // rounded W_proj

// ===========================================================================
// helpers
// ===========================================================================
__device__ __forceinline__ uint32_t smem_u32(const void* p) {
    uint32_t a;
    asm("{ .reg .u64 t; cvta.to.shared.u64 t, %1; cvt.u32.u64 %0, t; }"
        : "=r"(a) : "l"(p));
    return a;
}

__device__ __forceinline__ uint32_t f2tf32(float f) {
    uint32_t r;
    asm("cvt.rna.tf32.f32 %0, %1;" : "=r"(r) : "f"(f));
    return r;
}

#define CP_ASYNC16(dst_u32, src_ptr) \
    asm volatile("cp.async.cg.shared.global [%0], [%1], 16;" \
        :: "r"(dst_u32), "l"(src_ptr) : "memory")
#define CP_COMMIT() asm volatile("cp.async.commit_group;" ::: "memory")
#define CP_WAIT(n)  asm volatile("cp.async.wait_group %0;" :: "n"(n) : "memory")

__device__ __forceinline__ void mma_tf32(float* d, const uint32_t* a, const uint32_t* b) {
    asm volatile(
        "mma.sync.aligned.m16n8k8.row.col.f32.tf32.tf32.f32 "
        "{%0,%1,%2,%3}, {%4,%5,%6,%7}, {%8,%9}, {%0,%1,%2,%3};"
        : "+f"(d[0]), "+f"(d[1]), "+f"(d[2]), "+f"(d[3])
        : "r"(a[0]), "r"(a[1]), "r"(a[2]), "r"(a[3]), "r"(b[0]), "r"(b[1]));
}

// ===========================================================================
// tf32 pre-round pass
// ===========================================================================
__global__ __launch_bounds__(256) void round_tf32_kernel(
    const float4* __restrict__ src, float4* __restrict__ dst, int n4)
{
    int i = blockIdx.x * blockDim.x + threadIdx.x;
    if (i < n4) {
        float4 v = src[i];
        float4 r;
        r.x = __uint_as_float(f2tf32(v.x));
        r.y = __uint_as_float(f2tf32(v.y));
        r.z = __uint_as_float(f2tf32(v.z));
        r.w = __uint_as_float(f2tf32(v.w));
        dst[i] = r;
    }
}

// ===========================================================================
// TF32 mma.sync GEMM: C[M,N] = A[M,K] @ B[K,N] + bias[N]
// Pre-rounded operands; 3-stage cp.async ring (ONE barrier per K-tile);
// 2 CTAs/SM via launch bounds (regs fit exactly: 2*256*128 = 64K).
// ===========================================================================
#define BM 128
#define BN 128
#define BKT 32
#define A_STRIDE 36
#define B_STRIDE 136
#define A_BUF_FLOATS (BM * A_STRIDE)
#define B_BUF_FLOATS (BKT * B_STRIDE)
#define STAGE_FLOATS (A_BUF_FLOATS + B_BUF_FLOATS)
#define GEMM_SMEM_BYTES (3 * STAGE_FLOATS * 4)     // 107520

__global__ __launch_bounds__(256, 2) void gemm_tc_kernel(
    const float* __restrict__ A, const float* __restrict__ B,
    const float* __restrict__ bias, float* __restrict__ C,
    int M, int N, int K, int roundOut)
{
    extern __shared__ float sm[];
    const uint32_t sm_u = smem_u32(sm);

    const int tid  = threadIdx.x;
    const int wid  = tid >> 5;
    const int lane = tid & 31;
    const int g    = lane >> 2;
    const int tg   = lane & 3;
    const int warpM = (wid & 3) * 32;
    const int warpN = (wid >> 2) * 64;
    const int rowBase = blockIdx.y * BM;
    const int colBase = blockIdx.x * BN;
    const int NT = K / BKT;

    // stage s occupies floats [s*STAGE_FLOATS, ...): A first, then B.
    auto issue_tile = [&](int kt, int buf) {
        const float* Ap = A + (size_t)rowBase * K + kt * BKT;
        uint32_t adst = sm_u + (uint32_t)(buf * STAGE_FLOATS) * 4;
        #pragma unroll
        for (int i = 0; i < 4; i++) {
            int f = tid + 256 * i;
            int r = f >> 3, c = f & 7;
            CP_ASYNC16(adst + (uint32_t)(r * A_STRIDE + c * 4) * 4,
                       Ap + (size_t)r * K + c * 4);
        }
        const float* Bp = B + (size_t)(kt * BKT) * N + colBase;
        uint32_t bdst = adst + (uint32_t)A_BUF_FLOATS * 4;
        #pragma unroll
        for (int i = 0; i < 4; i++) {
            int f = tid + 256 * i;
            int k = f >> 5, c = f & 31;
            CP_ASYNC16(bdst + (uint32_t)(k * B_STRIDE + c * 4) * 4,
                       Bp + (size_t)k * N + c * 4);
        }
        CP_COMMIT();
    };

    float acc[2][8][4];
    #pragma unroll
    for (int mt = 0; mt < 2; mt++)
        #pragma unroll
        for (int nt = 0; nt < 8; nt++)
            #pragma unroll
            for (int e = 0; e < 4; e++) acc[mt][nt][e] = 0.0f;

    issue_tile(0, 0);
    issue_tile(1, 1);

    int buf = 0;
    for (int kt = 0; kt < NT; kt++) {
        CP_WAIT(1);              // tile kt resident
        __syncthreads();         // all warps see it; all done computing kt-1
        if (kt + 2 < NT) {
            int nb = buf + 2; if (nb >= 3) nb -= 3;
            issue_tile(kt + 2, nb);   // buffer of tile kt-1: free after barrier
        }

        const uint32_t* Ab = (const uint32_t*)(sm + buf * STAGE_FLOATS);
        const uint32_t* Bb = Ab + A_BUF_FLOATS;

        #pragma unroll
        for (int s = 0; s < 4; s++) {
            uint32_t af[2][4], bf[8][2];
            #pragma unroll
            for (int mt = 0; mt < 2; mt++) {
                const uint32_t* ap = Ab + (warpM + mt * 16 + g) * A_STRIDE + s * 8 + tg;
                af[mt][0] = ap[0];
                af[mt][1] = ap[8 * A_STRIDE];
                af[mt][2] = ap[4];
                af[mt][3] = ap[8 * A_STRIDE + 4];
            }
            #pragma unroll
            for (int nt = 0; nt < 8; nt++) {
                const uint32_t* bp = Bb + (s * 8 + tg) * B_STRIDE + warpN + nt * 8 + g;
                bf[nt][0] = bp[0];
                bf[nt][1] = bp[4 * B_STRIDE];
            }
            #pragma unroll
            for (int mt = 0; mt < 2; mt++)
                #pragma unroll
                for (int nt = 0; nt < 8; nt++)
                    mma_tf32(acc[mt][nt], af[mt], bf[nt]);
        }

        if (++buf == 3) buf = 0;
    }

    #pragma unroll
    for (int mt = 0; mt < 2; mt++) {
        #pragma unroll
        for (int nt = 0; nt < 8; nt++) {
            int col = colBase + warpN + nt * 8 + 2 * tg;
            float2 bb = *(const float2*)&bias[col];
            int row0 = rowBase + warpM + mt * 16 + g;
            float2 v0 = { acc[mt][nt][0] + bb.x, acc[mt][nt][1] + bb.y };
            float2 v1 = { acc[mt][nt][2] + bb.x, acc[mt][nt][3] + bb.y };
            if (roundOut) {
                v0.x = __uint_as_float(f2tf32(v0.x));
                v0.y = __uint_as_float(f2tf32(v0.y));
                v1.x = __uint_as_float(f2tf32(v1.x));
                v1.y = __uint_as_float(f2tf32(v1.y));
            }
            *(float2*)&C[(size_t)row0 * N + col] = v0;
            *(float2*)&C[(size_t)(row0 + 8) * N + col] = v1;
        }
    }
}

// ===========================================================================
// Flash attention (causal) on mma.sync TF32; 2 CTAs/SM target.
// ===========================================================================
#define ABR 128
#define ABC 64
#define ASTR 68
#define AK0 0
#define AV0 (ABC * ASTR)
#define AK1 (2 * ABC * ASTR)
#define AV1 (3 * ABC * ASTR)
#define APS (4 * ABC * ASTR)
#define ATTN_SMEM_FLOATS (APS + 8 * 16 * ASTR)
#define ATTN_SMEM_BYTES (ATTN_SMEM_FLOATS * 4)     // 104448

__global__ __launch_bounds__(256, 2) void attn_tc_kernel(
    const float* __restrict__ qkv, float* __restrict__ y)
{
    extern __shared__ float sm[];
    const uint32_t sm32 = smem_u32(sm);

    const int qt = (gridDim.x - 1) - blockIdx.x;
    const int h  = blockIdx.y;
    const int b  = blockIdx.z;
    const int tid  = threadIdx.x;
    const int wid  = tid >> 5;
    const int lane = tid & 31;
    const int g    = lane >> 2;
    const int tg   = lane & 3;
    const int qrow0 = qt * ABR;
    const int rw    = wid * 16;
    float* Pw = sm + APS + wid * (16 * ASTR);

    // ---- stage Q (coalesced) into P region, read A-fragments (pre-rounded)
    {
        const float* qg = qkv + (size_t)(b * T_SEQ + qrow0) * C3 + h * HD;
        #pragma unroll
        for (int i = 0; i < 8; i++) {
            int f = tid + 256 * i;
            int row = f >> 4;
            int c4  = (f & 15) << 2;
            *(float4*)&sm[APS + (row >> 4) * (16 * ASTR) + (row & 15) * ASTR + c4] =
                *(const float4*)(qg + (size_t)row * C3 + c4);
        }
    }
    __syncthreads();
    uint32_t qf[8][4];
    #pragma unroll
    for (int s = 0; s < 8; s++) {
        const uint32_t* qp = (const uint32_t*)(Pw + g * ASTR + s * 8 + tg);
        qf[s][0] = qp[0];
        qf[s][1] = qp[8 * ASTR];
        qf[s][2] = qp[4];
        qf[s][3] = qp[8 * ASTR + 4];
    }

    float o[8][4];
    #pragma unroll
    for (int nt = 0; nt < 8; nt++)
        #pragma unroll
        for (int e = 0; e < 4; e++) o[nt][e] = 0.0f;
    float m0 = -1e30f, m1 = -1e30f, l0 = 0.0f, l1 = 0.0f;
    const float scale = 0.125f;

    const int KT = 2 * qt + 2;

    auto issue = [&](int kt, int buf) {
        const float* kb = qkv + (size_t)(b * T_SEQ + kt * ABC) * C3 + C_EMB + h * HD;
        const float* vb = kb + C_EMB;
        uint32_t kdst = sm32 + (buf ? AK1 : AK0) * 4;
        uint32_t vdst = sm32 + (buf ? AV1 : AV0) * 4;
        #pragma unroll
        for (int i = 0; i < 4; i++) {
            int f = tid + 256 * i;
            int row = f >> 4, c = f & 15;
            CP_ASYNC16(kdst + (uint32_t)(row * ASTR + c * 4) * 4,
                       kb + (size_t)row * C3 + c * 4);
        }
        #pragma unroll
        for (int i = 0; i < 4; i++) {
            int f = tid + 256 * i;
            int row = f >> 4, c = f & 15;
            CP_ASYNC16(vdst + (uint32_t)(row * ASTR + c * 4) * 4,
                       vb + (size_t)row * C3 + c * 4);
        }
        CP_COMMIT();
    };

    issue(0, 0);
    for (int kt = 0; kt < KT; kt++) {
        if (kt + 1 < KT) { issue(kt + 1, (kt + 1) & 1); CP_WAIT(1); }
        else             { CP_WAIT(0); }
        __syncthreads();

        const uint32_t* Kb = (const uint32_t*)(sm + ((kt & 1) ? AK1 : AK0));
        const uint32_t* Vb = (const uint32_t*)(sm + ((kt & 1) ? AV1 : AV0));

        bool alive = (kt * ABC) <= (qrow0 + rw + 15);
        if (alive) {
            // ---- S = Q K^T
            float sa[8][4];
            #pragma unroll
            for (int nt = 0; nt < 8; nt++)
                #pragma unroll
                for (int e = 0; e < 4; e++) sa[nt][e] = 0.0f;
            #pragma unroll
            for (int s = 0; s < 8; s++) {
                #pragma unroll
                for (int nt = 0; nt < 8; nt++) {
                    uint32_t bf[2];
                    const uint32_t* kp = Kb + (nt * 8 + g) * ASTR + s * 8 + tg;
                    bf[0] = kp[0];
                    bf[1] = kp[4];
                    mma_tf32(sa[nt], qf[s], bf);
                }
            }

            // ---- mask + online softmax
            bool band = (kt * ABC + ABC - 1) > (qrow0 + rw);
            int grow0 = qrow0 + rw + g;
            int gcol0 = kt * ABC + 2 * tg;
            float mx0 = m0, mx1 = m1;
            #pragma unroll
            for (int nt = 0; nt < 8; nt++) {
                int c0 = gcol0 + nt * 8;
                float v0 = sa[nt][0] * scale;
                float v1 = sa[nt][1] * scale;
                float v2 = sa[nt][2] * scale;
                float v3 = sa[nt][3] * scale;
                if (band) {
                    if (c0     > grow0)     v0 = -1e30f;
                    if (c0 + 1 > grow0)     v1 = -1e30f;
                    if (c0     > grow0 + 8) v2 = -1e30f;
                    if (c0 + 1 > grow0 + 8) v3 = -1e30f;
                }
                sa[nt][0] = v0; sa[nt][1] = v1; sa[nt][2] = v2; sa[nt][3] = v3;
                mx0 = fmaxf(mx0, fmaxf(v0, v1));
                mx1 = fmaxf(mx1, fmaxf(v2, v3));
            }
            mx0 = fmaxf(mx0, __shfl_xor_sync(0xffffffffu, mx0, 1));
            mx0 = fmaxf(mx0, __shfl_xor_sync(0xffffffffu, mx0, 2));
            mx1 = fmaxf(mx1, __shfl_xor_sync(0xffffffffu, mx1, 1));
            mx1 = fmaxf(mx1, __shfl_xor_sync(0xffffffffu, mx1, 2));
            float corr0 = __expf(m0 - mx0);
            float corr1 = __expf(m1 - mx1);
            m0 = mx0; m1 = mx1;

            float ls0 = 0.0f, ls1 = 0.0f;
            #pragma unroll
            for (int nt = 0; nt < 8; nt++) {
                float p0 = __expf(sa[nt][0] - m0);
                float p1 = __expf(sa[nt][1] - m0);
                float p2 = __expf(sa[nt][2] - m1);
                float p3 = __expf(sa[nt][3] - m1);
                sa[nt][0] = p0; sa[nt][1] = p1; sa[nt][2] = p2; sa[nt][3] = p3;
                ls0 += p0 + p1;
                ls1 += p2 + p3;
            }
            l0 = l0 * corr0 + ls0;
            l1 = l1 * corr1 + ls1;
            #pragma unroll
            for (int nt = 0; nt < 8; nt++) {
                o[nt][0] *= corr0; o[nt][1] *= corr0;
                o[nt][2] *= corr1; o[nt][3] *= corr1;
            }

            // ---- P -> smem (warp-private), reread as A-fragments (CVT here)
            __syncwarp();
            #pragma unroll
            for (int nt = 0; nt < 8; nt++) {
                *(float2*)&Pw[g * ASTR + nt * 8 + 2 * tg]       = *(float2*)&sa[nt][0];
                *(float2*)&Pw[(g + 8) * ASTR + nt * 8 + 2 * tg] = *(float2*)&sa[nt][2];
            }
            __syncwarp();

            // ---- O += P V
            #pragma unroll
            for (int s = 0; s < 8; s++) {
                uint32_t pf[4];
                const float* pp = Pw + g * ASTR + s * 8 + tg;
                pf[0] = f2tf32(pp[0]);
                pf[1] = f2tf32(pp[8 * ASTR]);
                pf[2] = f2tf32(pp[4]);
                pf[3] = f2tf32(pp[8 * ASTR + 4]);
                #pragma unroll
                for (int nt = 0; nt < 8; nt++) {
                    uint32_t bf[2];
                    const uint32_t* vp = Vb + (s * 8 + tg) * ASTR + nt * 8 + g;
                    bf[0] = vp[0];
                    bf[1] = vp[4 * ASTR];
                    mma_tf32(o[nt], pf, bf);
                }
            }
        }
        __syncthreads();
    }

    // ---- final l reduction + normalize + write (tf32-rounded for proj GEMM)
    l0 += __shfl_xor_sync(0xffffffffu, l0, 1);
    l0 += __shfl_xor_sync(0xffffffffu, l0, 2);
    l1 += __shfl_xor_sync(0xffffffffu, l1, 1);
    l1 += __shfl_xor_sync(0xffffffffu, l1, 2);
    float inv0 = 1.0f / l0;
    float inv1 = 1.0f / l1;

    int row0 = b * T_SEQ + qrow0 + rw + g;
    #pragma unroll
    for (int nt = 0; nt < 8; nt++) {
        int col = h * HD + nt * 8 + 2 * tg;
        float2 v0 = { __uint_as_float(f2tf32(o[nt][0] * inv0)),
                      __uint_as_float(f2tf32(o[nt][1] * inv0)) };
        float2 v1 = { __uint_as_float(f2tf32(o[nt][2] * inv1)),
                      __uint_as_float(f2tf32(o[nt][3] * inv1)) };
        *(float2*)&y[(size_t)row0 * C_EMB + col] = v0;
        *(float2*)&y[(size_t)(row0 + 8) * C_EMB + col] = v1;
    }
}

// ===========================================================================
extern "C" void kernel_launch(void* const* d_in, const int* in_sizes, int n_in,
                              void* d_out, int out_size)
{
    const float* x      = (const float*)d_in[0];
    const float* W_attn = (const float*)d_in[1];
    const float* b_attn = (const float*)d_in[2];
    const float* W_proj = (const float*)d_in[3];
    const float* b_proj = (const float*)d_in[4];
    float* out = (float*)d_out;

    float *qkv, *yb, *xr, *war, *wpr;
    cudaGetSymbolAddress((void**)&qkv, g_qkv);
    cudaGetSymbolAddress((void**)&yb,  g_y);
    cudaGetSymbolAddress((void**)&xr,  g_xr);
    cudaGetSymbolAddress((void**)&war, g_war);
    cudaGetSymbolAddress((void**)&wpr, g_wpr);

    cudaFuncSetAttribute(gemm_tc_kernel,
                         cudaFuncAttributeMaxDynamicSharedMemorySize, GEMM_SMEM_BYTES);
    cudaFuncSetAttribute(attn_tc_kernel,
                         cudaFuncAttributeMaxDynamicSharedMemorySize, ATTN_SMEM_BYTES);

    // 0) pre-round inputs to tf32 (once; hot loops then run CVT-free)
    {
        int n4x = (M_ROWS * C_EMB) / 4;
        int n4a = (C_EMB * C3) / 4;
        int n4p = (C_EMB * C_EMB) / 4;
        round_tf32_kernel<<<n4x / 256, 256>>>((const float4*)x, (float4*)xr, n4x);
        round_tf32_kernel<<<n4a / 256, 256>>>((const float4*)W_attn, (float4*)war, n4a);
        round_tf32_kernel<<<n4p / 256, 256>>>((const float4*)W_proj, (float4*)wpr, n4p);
    }

    // 1) qkv = x_r @ Wa_r + b_attn  (epilogue writes tf32-rounded qkv)
    gemm_tc_kernel<<<dim3(C3 / BN, M_ROWS / BM), 256, GEMM_SMEM_BYTES>>>(
        xr, war, b_attn, qkv, M_ROWS, C3, C_EMB, 1);

    // 2) causal flash attention -> y (tf32-rounded)
    attn_tc_kernel<<<dim3(T_SEQ / ABR, NH, BATCH), 256, ATTN_SMEM_BYTES>>>(qkv, yb);

    // 3) out = y @ Wp_r + b_proj  (final output: NOT rounded)
    gemm_tc_kernel<<<dim3(C_EMB / BN, M_ROWS / BM), 256, GEMM_SMEM_BYTES>>>(
        yb, wpr, b_proj, out, M_ROWS, C_EMB, C_EMB, 0);
}